// round 15
// baseline (speedup 1.0000x reference)
#include <cuda_runtime.h>
#include <cstdint>
#include <math.h>

// B=2, S=2048, D=2048, H=16, HD=128, LY=512, DY=2048, H*HD=2048
#define NROWS_X 4096
#define NROWS_Y 1024
#define NH      2048

// ---------------- scratch ----------------
__device__ float g_xq[(size_t)NROWS_X * NH];
__device__ float g_xk[(size_t)NROWS_X * NH];
__device__ float g_xv[(size_t)NROWS_X * NH];
__device__ float g_yk[(size_t)NROWS_Y * NH];
__device__ float g_yv[(size_t)NROWS_Y * NH];
__device__ float g_at[(size_t)NROWS_X * NH];
__device__ float g_xt[(size_t)NROWS_X * 2048];
__device__ float g_yt[(size_t)NROWS_Y * 2048];
__device__ float g_wt[(size_t)6 * 2048 * 2048];

// ---------------- helpers ----------------
__device__ __forceinline__ uint32_t f2tf(float f) {
    uint32_t u;
    asm("cvt.rna.tf32.f32 %0, %1;" : "=r"(u) : "f"(f));
    return u;
}
__device__ __forceinline__ uint32_t bits(float f) { return __float_as_uint(f); }

__device__ __forceinline__ void mma_tf32(float c[4],
    uint32_t a0, uint32_t a1, uint32_t a2, uint32_t a3,
    uint32_t b0, uint32_t b1)
{
    asm volatile(
        "mma.sync.aligned.m16n8k8.row.col.f32.tf32.tf32.f32 "
        "{%0,%1,%2,%3}, {%4,%5,%6,%7}, {%8,%9}, {%0,%1,%2,%3};"
        : "+f"(c[0]), "+f"(c[1]), "+f"(c[2]), "+f"(c[3])
        : "r"(a0), "r"(a1), "r"(a2), "r"(a3), "r"(b0), "r"(b1));
}

__device__ __forceinline__ void ldsm4(uint32_t r[4], uint32_t addr)
{
    asm volatile("ldmatrix.sync.aligned.m8n8.x4.shared.b16 {%0,%1,%2,%3}, [%4];"
        : "=r"(r[0]), "=r"(r[1]), "=r"(r[2]), "=r"(r[3]) : "r"(addr));
}

__device__ __forceinline__ void cpa16(uint32_t dst, const void* src) {
    asm volatile("cp.async.cg.shared.global [%0], [%1], 16;" :: "r"(dst), "l"(src));
}
__device__ __forceinline__ void cpcommit() { asm volatile("cp.async.commit_group;" ::); }
__device__ __forceinline__ void cpwait1()  { asm volatile("cp.async.wait_group 1;" ::); }

__device__ __forceinline__ float neginf() { return __int_as_float(0xff800000); }

// ------------- prologue: fused elementwise tf32 round (x and y) -------------
__global__ __launch_bounds__(256) void cvt2_tf32_kernel(
    const float* __restrict__ in0, float* __restrict__ out0, int n0,
    const float* __restrict__ in1, float* __restrict__ out1, int n1)
{
    const float* in = blockIdx.y ? in1 : in0;
    float* out = blockIdx.y ? out1 : out0;
    int n = blockIdx.y ? n1 : n0;
    int i = (blockIdx.x * 256 + threadIdx.x) * 4;
    if (i < n) {
        float4 v = *(const float4*)(in + i);
        uint4 u = make_uint4(f2tf(v.x), f2tf(v.y), f2tf(v.z), f2tf(v.w));
        *(uint4*)(out + i) = u;
    }
}

// ------------- prologue: 6x fused 2048x2048 transpose + tf32 round --------------
__global__ __launch_bounds__(256) void transpose6_cvt_kernel(
    const float* s0, const float* s1, const float* s2,
    const float* s3, const float* s4, const float* s5, float* dbase)
{
    const float* S[6] = { s0, s1, s2, s3, s4, s5 };
    const float* W = S[blockIdx.z];
    float* Wt = dbase + (size_t)blockIdx.z * 2048 * 2048;

    __shared__ float tile[32][33];
    int x = blockIdx.x * 32 + threadIdx.x;
    int y0 = blockIdx.y * 32;
#pragma unroll
    for (int j = threadIdx.y; j < 32; j += 8)
        tile[j][threadIdx.x] = W[(size_t)(y0 + j) * 2048 + x];
    __syncthreads();
    int xo = blockIdx.y * 32 + threadIdx.x;
    int yo0 = blockIdx.x * 32;
#pragma unroll
    for (int j = threadIdx.y; j < 32; j += 8)
        Wt[(size_t)(yo0 + j) * 2048 + xo] = __uint_as_float(f2tf(tile[threadIdx.x][j]));
}

// ========= TF32 GEMM v5 (z-batched): BK=32, 3-stage cp.async, ldmatrix =========
// Per z: C[M,N] = A[M,K] @ Bt^T. A row-major [M,K], Bt row-major [N,K], tf32-valued.
// 128x128x32 tile, 256 thr (8 warps 2x4), warp 64x32 via 4x4 m16n8k8.
// Inner body = proven R9 body executed twice per barrier (halves barrier count).
#define GS_LD  36
#define GS_STG (128 * GS_LD)        // 4608 floats per stage per tensor
#define GOF_B  (3 * GS_STG)         // 13824
#define G_TOT  (6 * GS_STG)         // 27648 floats = 110592 B

__global__ __launch_bounds__(256, 2) void gemm_tf32_b3(
    const float* __restrict__ A,
    const float* __restrict__ B0, const float* __restrict__ B1, const float* __restrict__ B2,
    float* __restrict__ C0, float* __restrict__ C1, float* __restrict__ C2,
    int M, int N, int K, int cvt_mask)
{
    extern __shared__ float gsm[];
    const float* Bt = (blockIdx.z == 0) ? B0 : ((blockIdx.z == 1) ? B1 : B2);
    float* C = (blockIdx.z == 0) ? C0 : ((blockIdx.z == 1) ? C1 : C2);
    const int cvt_out = (cvt_mask >> blockIdx.z) & 1;

    const int t = threadIdx.x, lane = t & 31, wid = t >> 5;
    const int wm = wid >> 2, wn = wid & 3;
    const int g = lane >> 2, c = lane & 3;
    const int m0 = blockIdx.y * 128, n0 = blockIdx.x * 128;

    const uint32_t smb = (uint32_t)__cvta_generic_to_shared(gsm);
    // fill mapping: 32 cols/stage; 8 threads per row, 32 rows per pass, 4 passes
    const int frow = t >> 3, fcol = (t & 7) * 4;
    const float* Ag = A + (size_t)(m0 + frow) * K + fcol;
    const float* Bg = Bt + (size_t)(n0 + frow) * K + fcol;
    const uint32_t aS = smb + (frow * GS_LD + fcol) * 4;
    const uint32_t bS = aS + GOF_B * 4;
    const int niter = K >> 5;   // 64

    const uint32_t a_loff = (((lane & 15) * GS_LD + ((lane & 16) ? 4 : 0)) * 4);
    const uint32_t b_loff = (((lane & 7) * GS_LD + ((lane >> 3) & 3) * 4) * 4);
    const uint32_t a_base = smb + (wm * 64 * GS_LD) * 4 + a_loff;
    const uint32_t b_base = smb + GOF_B * 4 + (wn * 32 * GS_LD) * 4 + b_loff;

    float acc[4][4][4];
#pragma unroll
    for (int i = 0; i < 4; ++i)
#pragma unroll
        for (int j = 0; j < 4; ++j)
#pragma unroll
            for (int k = 0; k < 4; ++k) acc[i][j][k] = 0.f;

#define G_FILL(K0) do { \
        uint32_t so_ = (uint32_t)((K0) % 3) * (GS_STG * 4); \
        const float* ag_ = Ag + (K0) * 32; \
        const float* bg_ = Bg + (K0) * 32; \
        cpa16(aS + so_,                      ag_); \
        cpa16(aS + so_ + 32 * GS_LD * 4,     ag_ + (size_t)32 * K); \
        cpa16(aS + so_ + 64 * GS_LD * 4,     ag_ + (size_t)64 * K); \
        cpa16(aS + so_ + 96 * GS_LD * 4,     ag_ + (size_t)96 * K); \
        cpa16(bS + so_,                      bg_); \
        cpa16(bS + so_ + 32 * GS_LD * 4,     bg_ + (size_t)32 * K); \
        cpa16(bS + so_ + 64 * GS_LD * 4,     bg_ + (size_t)64 * K); \
        cpa16(bS + so_ + 96 * GS_LD * 4,     bg_ + (size_t)96 * K); \
    } while (0)

    G_FILL(0); cpcommit();
    G_FILL(1); cpcommit();

    for (int k0 = 0; k0 < niter; ++k0) {
        cpwait1();
        __syncthreads();   // stage k0 ready; all warps past stage (k0-1)'s compute
        if (k0 + 2 < niter) G_FILL(k0 + 2);
        cpcommit();

        const uint32_t so = (uint32_t)(k0 % 3) * (GS_STG * 4);
#pragma unroll
        for (int half = 0; half < 2; ++half) {
            uint32_t b[4][4];
#pragma unroll
            for (int ni = 0; ni < 4; ++ni)
                ldsm4(b[ni], b_base + so + (ni * 8 * GS_LD + half * 16) * 4);
#pragma unroll
            for (int ks = 0; ks < 2; ++ks) {
#pragma unroll
                for (int mi = 0; mi < 4; ++mi) {
                    uint32_t a[4];
                    ldsm4(a, a_base + so + (mi * 16 * GS_LD + (half * 2 + ks) * 8) * 4);
#pragma unroll
                    for (int ni = 0; ni < 4; ++ni)
                        mma_tf32(acc[mi][ni], a[0], a[1], a[2], a[3],
                                 b[ni][2 * ks], b[ni][2 * ks + 1]);
                }
            }
        }
    }
#pragma unroll
    for (int mi = 0; mi < 4; ++mi)
#pragma unroll
        for (int ni = 0; ni < 4; ++ni) {
            int row = m0 + wm * 64 + mi * 16 + g;
            int col = n0 + wn * 32 + ni * 8 + 2 * c;
            float2 v0 = make_float2(acc[mi][ni][0], acc[mi][ni][1]);
            float2 v1 = make_float2(acc[mi][ni][2], acc[mi][ni][3]);
            if (cvt_out) {
                v0.x = __uint_as_float(f2tf(v0.x)); v0.y = __uint_as_float(f2tf(v0.y));
                v1.x = __uint_as_float(f2tf(v1.x)); v1.y = __uint_as_float(f2tf(v1.y));
            }
            *(float2*)&C[(size_t)row * N + col] = v0;
            *(float2*)&C[(size_t)(row + 8) * N + col] = v1;
        }
}

// --------- fused LayerNorm x3 (+ optional RoPE); output scaled + tf32-rounded ----
__global__ __launch_bounds__(256) void ln3_kernel(
    float* X0, const float* w0, const float* b0,
    float* X1, const float* w1, const float* b1,
    float* X2, const float* w2, const float* b2,
    const float* __restrict__ fc, float qscl)
{
    const int z = blockIdx.y;
    const int row = blockIdx.x;
    if (z == 2 && row >= NROWS_Y) return;
    float* X = (z == 0) ? X0 : ((z == 1) ? X1 : X2);
    const float* w = (z == 0) ? w0 : ((z == 1) ? w1 : w2);
    const float* bgain = (z == 0) ? b0 : ((z == 1) ? b1 : b2);
    const float eps = (z == 2) ? 1e-6f : 1e-5f;
    const int do_rope = (z != 2);
    const float scl = (z == 0) ? qscl : 1.0f;

    float* xr = X + (size_t)row * 2048;
    const int t = threadIdx.x;

    float v[8];
    *(float4*)(v)     = *(const float4*)(xr + t * 8);
    *(float4*)(v + 4) = *(const float4*)(xr + t * 8 + 4);

    float s = 0.f, ss = 0.f;
#pragma unroll
    for (int i = 0; i < 8; ++i) { s += v[i]; ss += v[i] * v[i]; }
#pragma unroll
    for (int off = 16; off; off >>= 1) {
        s  += __shfl_xor_sync(0xffffffffu, s, off);
        ss += __shfl_xor_sync(0xffffffffu, ss, off);
    }
    __shared__ float sh[16];
    const int lane = t & 31, wrp = t >> 5;
    if (lane == 0) { sh[wrp] = s; sh[8 + wrp] = ss; }
    __syncthreads();
    s = 0.f; ss = 0.f;
#pragma unroll
    for (int i = 0; i < 8; ++i) { s += sh[i]; ss += sh[8 + i]; }

    const float mean = s * (1.f / 2048.f);
    const float var  = ss * (1.f / 2048.f) - mean * mean;
    const float rs   = rsqrtf(var + eps);

    const int base = t * 8;
    float o[8];
#pragma unroll
    for (int i = 0; i < 8; ++i) {
        int e = base + i;
        o[i] = (v[i] - mean) * rs * w[e] + bgain[e];
    }
    if (do_rope) {
        int sidx = row & 2047;
#pragma unroll
        for (int i = 0; i < 8; i += 2) {
            int e = base + i;
            int pidx = (e & 127) >> 1;
            float cc = fc[(sidx * 64 + pidx) * 2 + 0];
            float sn = fc[(sidx * 64 + pidx) * 2 + 1];
            float r0 = o[i] * cc - o[i + 1] * sn;
            float r1 = o[i] * sn + o[i + 1] * cc;
            o[i] = r0; o[i + 1] = r1;
        }
    }
#pragma unroll
    for (int i = 0; i < 8; ++i) o[i] = __uint_as_float(f2tf(o[i] * scl));
    *(float4*)(xr + t * 8)     = *(float4*)(o);
    *(float4*)(xr + t * 8 + 4) = *(float4*)(o + 4);
}

// ===== TF32 flash attention v6 (R12 winner): TQ=64, 128 threads, 2+ blocks/SM ====
#define AT_LDQ 132
#define AT_LDK 132
#define AT_LDV 136
#define AT_LDP 36
#define AOF_K (64 * AT_LDQ)            // 8448
#define AOF_V (AOF_K + 32 * AT_LDK)    // 12672
#define AOF_P (AOF_V + 32 * AT_LDV)    // 17024
#define AT_TOT (AOF_P + 64 * AT_LDP)   // 19328 floats = 77312 B

__device__ __forceinline__ void attn_pass_tc(
    const float* __restrict__ Kg, const float* __restrict__ Vg,
    size_t kv0, int ntiles, int hoff,
    float* smf, uint32_t smb, int t, float acc[16][4], float lout[2])
{
    const int lane = t & 31, wid = t >> 5;   // wid 0..3
    const int g = lane >> 2, c = lane & 3;
    float* Ks = smf + AOF_K;
    float* Vs = smf + AOF_V;
    float* Ps = smf + AOF_P;

    const uint32_t q_base = smb + (wid * 16 * AT_LDQ) * 4 +
        (((lane & 15) * AT_LDQ + ((lane & 16) ? 4 : 0)) * 4);
    const uint32_t k_base = smb + AOF_K * 4 +
        (((lane & 7) * AT_LDK + ((lane & 8) ? 4 : 0) + ((lane & 16) ? 8 : 0)) * 4);
    const uint32_t p_base = smb + (AOF_P + wid * 16 * AT_LDP) * 4 +
        (((lane & 15) * AT_LDP + ((lane & 16) ? 4 : 0)) * 4);

    float m0 = neginf(), m1 = neginf();
    float l0 = 0.f, l1 = 0.f;
#pragma unroll
    for (int i = 0; i < 16; ++i)
#pragma unroll
        for (int j = 0; j < 4; ++j) acc[i][j] = 0.f;

    float rK[32], rV[32];
    {
        const float* Kb = Kg + kv0 * 2048 + hoff;
        const float* Vb = Vg + kv0 * 2048 + hoff;
#pragma unroll
        for (int j = 0; j < 8; ++j) {
            int row = j * 4 + wid;
            *(float4*)&rK[j * 4] = *(const float4*)(Kb + (size_t)row * 2048 + lane * 4);
            *(float4*)&rV[j * 4] = *(const float4*)(Vb + (size_t)row * 2048 + lane * 4);
        }
    }

    for (int kt = 0; kt < ntiles; ++kt) {
        __syncthreads();
#pragma unroll
        for (int j = 0; j < 8; ++j) {
            int row = j * 4 + wid;
            uint4 uk = make_uint4(f2tf(rK[j * 4]), f2tf(rK[j * 4 + 1]),
                                  f2tf(rK[j * 4 + 2]), f2tf(rK[j * 4 + 3]));
            *(uint4*)(Ks + row * AT_LDK + lane * 4) = uk;
            uint4 uv = make_uint4(f2tf(rV[j * 4]), f2tf(rV[j * 4 + 1]),
                                  f2tf(rV[j * 4 + 2]), f2tf(rV[j * 4 + 3]));
            *(uint4*)(Vs + row * AT_LDV + lane * 4) = uv;
        }
        __syncthreads();
        if (kt + 1 < ntiles) {
            const float* Kb = Kg + (kv0 + (size_t)(kt + 1) * 32) * 2048 + hoff;
            const float* Vb = Vg + (kv0 + (size_t)(kt + 1) * 32) * 2048 + hoff;
#pragma unroll
            for (int j = 0; j < 8; ++j) {
                int row = j * 4 + wid;
                *(float4*)&rK[j * 4] = *(const float4*)(Kb + (size_t)row * 2048 + lane * 4);
                *(float4*)&rV[j * 4] = *(const float4*)(Vb + (size_t)row * 2048 + lane * 4);
            }
        }

        // ---- S = Q @ K^T ----
        float s[4][4];
#pragma unroll
        for (int ni = 0; ni < 4; ++ni)
#pragma unroll
            for (int j = 0; j < 4; ++j) s[ni][j] = 0.f;
#pragma unroll
        for (int ksA = 0; ksA < 16; ksA += 2) {
            uint32_t aA[4], aB[4];
            ldsm4(aA, q_base + ksA * 32);
            ldsm4(aB, q_base + ksA * 32 + 32);
#pragma unroll
            for (int ni = 0; ni < 4; ++ni) {
                uint32_t bb[4];
                ldsm4(bb, k_base + (ni * 8 * AT_LDK + ksA * 8) * 4);
                mma_tf32(s[ni], aA[0], aA[1], aA[2], aA[3], bb[0], bb[1]);
                mma_tf32(s[ni], aB[0], aB[1], aB[2], aB[3], bb[2], bb[3]);
            }
        }

        // ---- online softmax ----
        float rm0 = neginf(), rm1 = neginf();
#pragma unroll
        for (int ni = 0; ni < 4; ++ni) {
            rm0 = fmaxf(rm0, fmaxf(s[ni][0], s[ni][1]));
            rm1 = fmaxf(rm1, fmaxf(s[ni][2], s[ni][3]));
        }
#pragma unroll
        for (int off = 1; off <= 2; off <<= 1) {
            rm0 = fmaxf(rm0, __shfl_xor_sync(0xffffffffu, rm0, off));
            rm1 = fmaxf(rm1, __shfl_xor_sync(0xffffffffu, rm1, off));
        }
        float mn0 = fmaxf(m0, rm0), mn1 = fmaxf(m1, rm1);
        float co0 = __expf(m0 - mn0), co1 = __expf(m1 - mn1);
        float rs0 = 0.f, rs1 = 0.f;
        __syncwarp();
#pragma unroll
        for (int ni = 0; ni < 4; ++ni) {
            float p00 = __expf(s[ni][0] - mn0);
            float p01 = __expf(s[ni][1] - mn0);
            float p10 = __expf(s[ni][2] - mn1);
            float p11 = __expf(s[ni][3] - mn1);
            rs0 += p00 + p01;
            rs1 += p10 + p11;
            int pb = (wid * 16 + g) * AT_LDP + ni * 8 + 2 * c;
            Ps[pb]     = __uint_as_float(f2tf(p00));
            Ps[pb + 1] = __uint_as_float(f2tf(p01));
            Ps[pb + 8 * AT_LDP]     = __uint_as_float(f2tf(p10));
            Ps[pb + 8 * AT_LDP + 1] = __uint_as_float(f2tf(p11));
        }
        __syncwarp();
#pragma unroll
        for (int off = 1; off <= 2; off <<= 1) {
            rs0 += __shfl_xor_sync(0xffffffffu, rs0, off);
            rs1 += __shfl_xor_sync(0xffffffffu, rs1, off);
        }
        l0 = l0 * co0 + rs0;
        l1 = l1 * co1 + rs1;
        m0 = mn0; m1 = mn1;
#pragma unroll
        for (int ni = 0; ni < 16; ++ni) {
            acc[ni][0] *= co0; acc[ni][1] *= co0;
            acc[ni][2] *= co1; acc[ni][3] *= co1;
        }

        // ---- O += P @ V ----
#pragma unroll
        for (int ks = 0; ks < 4; ++ks) {
            uint32_t ap[4];
            ldsm4(ap, p_base + ks * 32);
#pragma unroll
            for (int ni = 0; ni < 16; ++ni) {
                int bb = (ks * 8 + c) * AT_LDV + ni * 8 + g;
                mma_tf32(acc[ni], ap[0], ap[1], ap[2], ap[3],
                         bits(Vs[bb]), bits(Vs[bb + 4 * AT_LDV]));
            }
        }
    }
    lout[0] = l0; lout[1] = l1;
}

__global__ __launch_bounds__(128) void attn_tc_kernel(
    const float* __restrict__ Q, const float* __restrict__ K, const float* __restrict__ V,
    const float* __restrict__ KY, const float* __restrict__ VY,
    const float* __restrict__ gate, float* __restrict__ O)
{
    extern __shared__ float smf[];
    float* Qs = smf;

    const int qt = blockIdx.x, h = blockIdx.y, b = blockIdx.z;
    const int t = threadIdx.x, lane = t & 31, wid = t >> 5;
    const int g = lane >> 2, c = lane & 3;
    const int hoff = h * 128;
    const size_t qrow0 = (size_t)b * 2048 + (size_t)qt * 64;
    const uint32_t smb = (uint32_t)__cvta_generic_to_shared(smf);

    const float* Qb = Q + qrow0 * 2048 + hoff;
#pragma unroll
    for (int i = 0; i < 16; ++i) {
        int id = i * 128 + t;
        int row = id >> 5, c4 = id & 31;
        *(float4*)(Qs + row * AT_LDQ + c4 * 4) =
            *(const float4*)(Qb + (size_t)row * 2048 + c4 * 4);
    }

    float acc[16][4], l[2];

    // ---- self attention ----
    attn_pass_tc(K, V, (size_t)b * 2048, 64, hoff, smf, smb, t, acc, l);
    float* Ob = O + qrow0 * 2048 + hoff;
    {
        float inv0 = 1.f / l[0], inv1 = 1.f / l[1];
        int row = wid * 16 + g;
#pragma unroll
        for (int ni = 0; ni < 16; ++ni) {
            int col = ni * 8 + 2 * c;
            *(float2*)(Ob + (size_t)row * 2048 + col) =
                make_float2(acc[ni][0] * inv0, acc[ni][1] * inv0);
            *(float2*)(Ob + (size_t)(row + 8) * 2048 + col) =
                make_float2(acc[ni][2] * inv1, acc[ni][3] * inv1);
        }
    }

    // ---- gated cross attention ----
    attn_pass_tc(KY, VY, (size_t)b * 512, 16, hoff, smf, smb, t, acc, l);
    {
        float tg = tanhf(gate[h]);
        float inv0 = tg / l[0], inv1 = tg / l[1];
        int row = wid * 16 + g;
#pragma unroll
        for (int ni = 0; ni < 16; ++ni) {
            int col = ni * 8 + 2 * c;
            float2 p0 = *(float2*)(Ob + (size_t)row * 2048 + col);
            float2 p1 = *(float2*)(Ob + (size_t)(row + 8) * 2048 + col);
            p0.x += acc[ni][0] * inv0; p0.y += acc[ni][1] * inv0;
            p1.x += acc[ni][2] * inv1; p1.y += acc[ni][3] * inv1;
            p0.x = __uint_as_float(f2tf(p0.x)); p0.y = __uint_as_float(f2tf(p0.y));
            p1.x = __uint_as_float(f2tf(p1.x)); p1.y = __uint_as_float(f2tf(p1.y));
            *(float2*)(Ob + (size_t)row * 2048 + col) = p0;
            *(float2*)(Ob + (size_t)(row + 8) * 2048 + col) = p1;
        }
    }
}

// -------------------------------- host side --------------------------------------
extern "C" void kernel_launch(void* const* d_in, const int* in_sizes, int n_in,
                              void* d_out, int out_size)
{
    const float* x    = (const float*)d_in[0];
    const float* fc   = (const float*)d_in[2];
    const float* y    = (const float*)d_in[3];
    const float* wq   = (const float*)d_in[5];
    const float* wk   = (const float*)d_in[6];
    const float* wv   = (const float*)d_in[7];
    const float* wo   = (const float*)d_in[8];
    const float* wky  = (const float*)d_in[9];
    const float* wvy  = (const float*)d_in[10];
    const float* gate = (const float*)d_in[11];
    const float* qnw  = (const float*)d_in[12];
    const float* qnb  = (const float*)d_in[13];
    const float* knw  = (const float*)d_in[14];
    const float* knb  = (const float*)d_in[15];
    const float* kynw = (const float*)d_in[16];
    const float* kynb = (const float*)d_in[17];
    float* out = (float*)d_out;

    float *xq, *xk, *xv, *yk, *yv, *at, *xt, *yt, *wt;
    cudaGetSymbolAddress((void**)&xq, g_xq);
    cudaGetSymbolAddress((void**)&xk, g_xk);
    cudaGetSymbolAddress((void**)&xv, g_xv);
    cudaGetSymbolAddress((void**)&yk, g_yk);
    cudaGetSymbolAddress((void**)&yv, g_yv);
    cudaGetSymbolAddress((void**)&at, g_at);
    cudaGetSymbolAddress((void**)&xt, g_xt);
    cudaGetSymbolAddress((void**)&yt, g_yt);
    cudaGetSymbolAddress((void**)&wt, g_wt);
    const size_t WSZ = (size_t)2048 * 2048;
    float* wqt = wt;            float* wkt = wt + WSZ;      float* wvt = wt + 2 * WSZ;
    float* wkyt = wt + 3 * WSZ; float* wvyt = wt + 4 * WSZ; float* wot = wt + 5 * WSZ;

    cudaFuncSetAttribute(gemm_tf32_b3, cudaFuncAttributeMaxDynamicSharedMemorySize, G_TOT * 4);
    cudaFuncSetAttribute(attn_tc_kernel, cudaFuncAttributeMaxDynamicSharedMemorySize, AT_TOT * 4);

    // #1: fused tf32 round of x and y
    cvt2_tf32_kernel<<<dim3(NROWS_X * 2048 / 1024, 2), 256>>>(
        x, xt, NROWS_X * 2048, y, yt, NROWS_Y * 2048);
    // #2: fused transpose+round of all 6 weights
    transpose6_cvt_kernel<<<dim3(64, 64, 6), dim3(32, 8)>>>(wq, wk, wv, wky, wvy, wo, wt);
    // #3: x projections (xq, xk raw for LN; xv tf32-rounded)
    gemm_tf32_b3<<<dim3(NH / 128, NROWS_X / 128, 3), 256, G_TOT * 4>>>(
        xt, wqt, wkt, wvt, xq, xk, xv, NROWS_X, NH, 2048, 0b100);
    // #4: y projections (yk raw for LN; yv tf32-rounded)
    gemm_tf32_b3<<<dim3(NH / 128, NROWS_Y / 128, 2), 256, G_TOT * 4>>>(
        yt, wkyt, wvyt, wvyt, yk, yv, yv, NROWS_Y, NH, 2048, 0b010);
    // #5: fused layernorms (+rope); Q pre-scaled by 1/sqrt(HD)
    ln3_kernel<<<dim3(NROWS_X, 3), 256>>>(
        xq, qnw, qnb, xk, knw, knb, yk, kynw, kynb, fc, 0.08838834764831845f);
    // #6: fused self + gated-cross attention (TQ=64, 4 warps, 2+ blocks/SM)
    attn_tc_kernel<<<dim3(32, 16, 2), 128, AT_TOT * 4>>>(xq, xk, xv, yk, yv, gate, at);
    // #7: output projection (full f32 store)
    gemm_tf32_b3<<<dim3(NH / 128, NROWS_X / 128, 1), 256, G_TOT * 4>>>(
        at, wot, wot, wot, out, out, out, NROWS_X, NH, 2048, 0);
}

// round 16
// speedup vs baseline: 1.6601x; 1.6601x over previous
#include <cuda_runtime.h>
#include <cuda_fp16.h>
#include <cstdint>
#include <math.h>

// B=2, S=2048, D=2048, H=16, HD=128, LY=512, DY=2048, H*HD=2048
#define NROWS_X 4096
#define NROWS_Y 1024
#define NH      2048

// ---------------- scratch ----------------
__device__ float  g_xq[(size_t)NROWS_X * NH];      // GEMM f32 out (LN input)
__device__ float  g_xk[(size_t)NROWS_X * NH];
__device__ float  g_yk[(size_t)NROWS_Y * NH];
__device__ __half g_xqh[(size_t)NROWS_X * NH];     // LN half out (attn input)
__device__ __half g_xkh[(size_t)NROWS_X * NH];
__device__ __half g_ykh[(size_t)NROWS_Y * NH];
__device__ __half g_xvh[(size_t)NROWS_X * NH];     // GEMM half out
__device__ __half g_yvh[(size_t)NROWS_Y * NH];
__device__ __half g_ath[(size_t)NROWS_X * NH];     // attention half out
__device__ __half g_xth[(size_t)NROWS_X * 2048];   // rounded activations
__device__ __half g_yth[(size_t)NROWS_Y * 2048];
__device__ __half g_wth[(size_t)6 * 2048 * 2048];  // transposed half weights

// ---------------- helpers ----------------
__device__ __forceinline__ void mma_f16(float c[4],
    uint32_t a0, uint32_t a1, uint32_t a2, uint32_t a3,
    uint32_t b0, uint32_t b1)
{
    asm volatile(
        "mma.sync.aligned.m16n8k16.row.col.f32.f16.f16.f32 "
        "{%0,%1,%2,%3}, {%4,%5,%6,%7}, {%8,%9}, {%0,%1,%2,%3};"
        : "+f"(c[0]), "+f"(c[1]), "+f"(c[2]), "+f"(c[3])
        : "r"(a0), "r"(a1), "r"(a2), "r"(a3), "r"(b0), "r"(b1));
}

__device__ __forceinline__ void ldsm4(uint32_t r[4], uint32_t addr)
{
    asm volatile("ldmatrix.sync.aligned.m8n8.x4.shared.b16 {%0,%1,%2,%3}, [%4];"
        : "=r"(r[0]), "=r"(r[1]), "=r"(r[2]), "=r"(r[3]) : "r"(addr));
}
__device__ __forceinline__ void ldsm4t(uint32_t r[4], uint32_t addr)
{
    asm volatile("ldmatrix.sync.aligned.m8n8.x4.trans.shared.b16 {%0,%1,%2,%3}, [%4];"
        : "=r"(r[0]), "=r"(r[1]), "=r"(r[2]), "=r"(r[3]) : "r"(addr));
}

__device__ __forceinline__ void cpa16(uint32_t dst, const void* src) {
    asm volatile("cp.async.cg.shared.global [%0], [%1], 16;" :: "r"(dst), "l"(src));
}
__device__ __forceinline__ void cpcommit() { asm volatile("cp.async.commit_group;" ::); }
__device__ __forceinline__ void cpwait2()  { asm volatile("cp.async.wait_group 2;" ::); }

__device__ __forceinline__ float neginf() { return __int_as_float(0xff800000); }

// ------------- prologue: fused elementwise f32 -> f16 round (x and y) -------------
__global__ __launch_bounds__(256) void cvt2_f16_kernel(
    const float* __restrict__ in0, __half* __restrict__ out0, int n0,
    const float* __restrict__ in1, __half* __restrict__ out1, int n1)
{
    const float* in = blockIdx.y ? in1 : in0;
    __half* out = blockIdx.y ? out1 : out0;
    int n = blockIdx.y ? n1 : n0;
    int i = (blockIdx.x * 256 + threadIdx.x) * 4;
    if (i < n) {
        float4 v = *(const float4*)(in + i);
        __half2 h0 = __floats2half2_rn(v.x, v.y);
        __half2 h1 = __floats2half2_rn(v.z, v.w);
        *(uint2*)(out + i) = make_uint2(*(uint32_t*)&h0, *(uint32_t*)&h1);
    }
}

// ------------- prologue: 6x fused 2048x2048 transpose + f16 round --------------
__global__ __launch_bounds__(256) void transpose6_f16_kernel(
    const float* s0, const float* s1, const float* s2,
    const float* s3, const float* s4, const float* s5, __half* dbase)
{
    const float* S[6] = { s0, s1, s2, s3, s4, s5 };
    const float* W = S[blockIdx.z];
    __half* Wt = dbase + (size_t)blockIdx.z * 2048 * 2048;

    __shared__ float tile[32][33];
    int x = blockIdx.x * 32 + threadIdx.x;
    int y0 = blockIdx.y * 32;
#pragma unroll
    for (int j = threadIdx.y; j < 32; j += 8)
        tile[j][threadIdx.x] = W[(size_t)(y0 + j) * 2048 + x];
    __syncthreads();
    int xo = blockIdx.y * 32 + threadIdx.x;
    int yo0 = blockIdx.x * 32;
#pragma unroll
    for (int j = threadIdx.y; j < 32; j += 8)
        Wt[(size_t)(yo0 + j) * 2048 + xo] = __float2half_rn(tile[threadIdx.x][j]);
}

// ======== FP16 GEMM (z-batched): m16n8k16, 128x128x32 tile, 4-stage cp.async =====
// Per z: C[M,N] = A[M,K] @ Bt^T. A [M,K] half, Bt [N,K] half. C f32 or f16 per mask.
// 256 thr (8 warps 2x4), warp 64x32 via 4x4 m16n8k16.
#define GH_LD  40                   // halves per row (32 data + 8 pad)
#define GH_STG (128 * GH_LD)        // 5120 halves per stage per tensor
#define GHOF_B (4 * GH_STG)         // 20480 halves
#define GH_TOT (8 * GH_STG)         // 40960 halves = 81920 B

__global__ __launch_bounds__(256, 2) void gemm_f16_b3(
    const __half* __restrict__ A,
    const __half* __restrict__ B0, const __half* __restrict__ B1, const __half* __restrict__ B2,
    void* __restrict__ C0, void* __restrict__ C1, void* __restrict__ C2,
    int M, int N, int K, int half_mask)
{
    extern __shared__ __half gsm[];
    const __half* Bt = (blockIdx.z == 0) ? B0 : ((blockIdx.z == 1) ? B1 : B2);
    void* Cv = (blockIdx.z == 0) ? C0 : ((blockIdx.z == 1) ? C1 : C2);
    const int out_half = (half_mask >> blockIdx.z) & 1;

    const int t = threadIdx.x, lane = t & 31, wid = t >> 5;
    const int wm = wid >> 2, wn = wid & 3;
    const int g = lane >> 2, c = lane & 3;
    const int m0 = blockIdx.y * 128, n0 = blockIdx.x * 128;

    const uint32_t smb = (uint32_t)__cvta_generic_to_shared(gsm);
    const int frow = t >> 1, fcolh = (t & 1) * 16;
    const __half* Ag = A + (size_t)(m0 + frow) * K + fcolh;
    const __half* Bg = Bt + (size_t)(n0 + frow) * K + fcolh;
    const uint32_t aS = smb + (frow * GH_LD + fcolh) * 2;
    const uint32_t bS = aS + GHOF_B * 2;
    const int niter = K >> 5;   // 64

    const uint32_t a_loff = ((lane & 15) * GH_LD + ((lane & 16) ? 8 : 0)) * 2;
    const uint32_t b_loff = ((lane & 7) * GH_LD + ((lane & 16) ? 8 * GH_LD : 0)
                             + ((lane & 8) ? 8 : 0)) * 2;
    const uint32_t a_base = smb + (wm * 64 * GH_LD) * 2 + a_loff;
    const uint32_t b_base = smb + GHOF_B * 2 + (wn * 32 * GH_LD) * 2 + b_loff;

    float acc[4][4][4];
#pragma unroll
    for (int i = 0; i < 4; ++i)
#pragma unroll
        for (int j = 0; j < 4; ++j)
#pragma unroll
            for (int k = 0; k < 4; ++k) acc[i][j][k] = 0.f;

#define GH_FILL(K0) do { \
        uint32_t so_ = (uint32_t)((K0) & 3) * (GH_STG * 2); \
        const __half* ag_ = Ag + (K0) * 32; \
        const __half* bg_ = Bg + (K0) * 32; \
        cpa16(aS + so_,      ag_); \
        cpa16(aS + so_ + 16, ag_ + 8); \
        cpa16(bS + so_,      bg_); \
        cpa16(bS + so_ + 16, bg_ + 8); \
    } while (0)

    GH_FILL(0); cpcommit();
    GH_FILL(1); cpcommit();
    GH_FILL(2); cpcommit();

    for (int k0 = 0; k0 < niter; ++k0) {
        cpwait2();
        __syncthreads();
        if (k0 + 3 < niter) GH_FILL(k0 + 3);
        cpcommit();

        const uint32_t so = (uint32_t)(k0 & 3) * (GH_STG * 2);
#pragma unroll
        for (int ks = 0; ks < 2; ++ks) {
            uint32_t bq[4][2];
#pragma unroll
            for (int np = 0; np < 2; ++np) {
                uint32_t r[4];
                ldsm4(r, b_base + so + (np * 16 * GH_LD + ks * 16) * 2);
                bq[np * 2 + 0][0] = r[0]; bq[np * 2 + 0][1] = r[1];
                bq[np * 2 + 1][0] = r[2]; bq[np * 2 + 1][1] = r[3];
            }
#pragma unroll
            for (int mi = 0; mi < 4; ++mi) {
                uint32_t a[4];
                ldsm4(a, a_base + so + (mi * 16 * GH_LD + ks * 16) * 2);
#pragma unroll
                for (int ni = 0; ni < 4; ++ni)
                    mma_f16(acc[mi][ni], a[0], a[1], a[2], a[3],
                            bq[ni][0], bq[ni][1]);
            }
        }
    }
#pragma unroll
    for (int mi = 0; mi < 4; ++mi)
#pragma unroll
        for (int ni = 0; ni < 4; ++ni) {
            int row = m0 + wm * 64 + mi * 16 + g;
            int col = n0 + wn * 32 + ni * 8 + 2 * c;
            if (out_half) {
                __half* Ch = (__half*)Cv;
                __half2 h0 = __floats2half2_rn(acc[mi][ni][0], acc[mi][ni][1]);
                __half2 h1 = __floats2half2_rn(acc[mi][ni][2], acc[mi][ni][3]);
                *(__half2*)(Ch + (size_t)row * N + col) = h0;
                *(__half2*)(Ch + (size_t)(row + 8) * N + col) = h1;
            } else {
                float* Cf = (float*)Cv;
                *(float2*)(Cf + (size_t)row * N + col) =
                    make_float2(acc[mi][ni][0], acc[mi][ni][1]);
                *(float2*)(Cf + (size_t)(row + 8) * N + col) =
                    make_float2(acc[mi][ni][2], acc[mi][ni][3]);
            }
        }
}

// --- fused LayerNorm x3 (+ optional RoPE); f32 in, scaled + f16-rounded out ---
__global__ __launch_bounds__(256) void ln3_kernel(
    const float* X0, const float* w0, const float* b0, __half* H0,
    const float* X1, const float* w1, const float* b1, __half* H1,
    const float* X2, const float* w2, const float* b2, __half* H2,
    const float* __restrict__ fc, float qscl)
{
    const int z = blockIdx.y;
    const int row = blockIdx.x;
    if (z == 2 && row >= NROWS_Y) return;
    const float* X = (z == 0) ? X0 : ((z == 1) ? X1 : X2);
    const float* w = (z == 0) ? w0 : ((z == 1) ? w1 : w2);
    const float* bgain = (z == 0) ? b0 : ((z == 1) ? b1 : b2);
    __half* H = (z == 0) ? H0 : ((z == 1) ? H1 : H2);
    const float eps = (z == 2) ? 1e-6f : 1e-5f;
    const int do_rope = (z != 2);
    const float scl = (z == 0) ? qscl : 1.0f;

    const float* xr = X + (size_t)row * 2048;
    const int t = threadIdx.x;

    float v[8];
    *(float4*)(v)     = *(const float4*)(xr + t * 8);
    *(float4*)(v + 4) = *(const float4*)(xr + t * 8 + 4);

    float s = 0.f, ss = 0.f;
#pragma unroll
    for (int i = 0; i < 8; ++i) { s += v[i]; ss += v[i] * v[i]; }
#pragma unroll
    for (int off = 16; off; off >>= 1) {
        s  += __shfl_xor_sync(0xffffffffu, s, off);
        ss += __shfl_xor_sync(0xffffffffu, ss, off);
    }
    __shared__ float sh[16];
    const int lane = t & 31, wrp = t >> 5;
    if (lane == 0) { sh[wrp] = s; sh[8 + wrp] = ss; }
    __syncthreads();
    s = 0.f; ss = 0.f;
#pragma unroll
    for (int i = 0; i < 8; ++i) { s += sh[i]; ss += sh[8 + i]; }

    const float mean = s * (1.f / 2048.f);
    const float var  = ss * (1.f / 2048.f) - mean * mean;
    const float rs   = rsqrtf(var + eps);

    const int base = t * 8;
    float o[8];
#pragma unroll
    for (int i = 0; i < 8; ++i) {
        int e = base + i;
        o[i] = (v[i] - mean) * rs * w[e] + bgain[e];
    }
    if (do_rope) {
        int sidx = row & 2047;
#pragma unroll
        for (int i = 0; i < 8; i += 2) {
            int e = base + i;
            int pidx = (e & 127) >> 1;
            float cc = fc[(sidx * 64 + pidx) * 2 + 0];
            float sn = fc[(sidx * 64 + pidx) * 2 + 1];
            float r0 = o[i] * cc - o[i + 1] * sn;
            float r1 = o[i] * sn + o[i + 1] * cc;
            o[i] = r0; o[i + 1] = r1;
        }
    }
    __half2 h0 = __floats2half2_rn(o[0] * scl, o[1] * scl);
    __half2 h1 = __floats2half2_rn(o[2] * scl, o[3] * scl);
    __half2 h2 = __floats2half2_rn(o[4] * scl, o[5] * scl);
    __half2 h3 = __floats2half2_rn(o[6] * scl, o[7] * scl);
    *(uint4*)(H + (size_t)row * 2048 + base) =
        make_uint4(*(uint32_t*)&h0, *(uint32_t*)&h1, *(uint32_t*)&h2, *(uint32_t*)&h3);
}

// ======== FP16 flash attention: TQ=64, 128 thr (4 warps), m16n8k16, trans-V ======
#define AH_LDQ 136
#define AH_LDK 136
#define AH_LDV 136
#define AH_LDP 40
#define AHOF_K (64 * AH_LDQ)            // 8704 halves
#define AHOF_V (AHOF_K + 32 * AH_LDK)   // 13056
#define AHOF_P (AHOF_V + 32 * AH_LDV)   // 17408
#define AH_TOT (AHOF_P + 64 * AH_LDP)   // 19968 halves = 39936 B

__device__ __forceinline__ void attn_pass_f16(
    const __half* __restrict__ Kg, const __half* __restrict__ Vg,
    size_t kv0, int ntiles, int hoff,
    __half* smh, uint32_t smb, int t, float acc[16][4], float lout[2])
{
    const int lane = t & 31, wid = t >> 5;   // wid 0..3
    const int g = lane >> 2, c = lane & 3;
    __half* Ks = smh + AHOF_K;
    __half* Vs = smh + AHOF_V;
    __half* Ps = smh + AHOF_P;

    const uint32_t q_base = smb + (wid * 16 * AH_LDQ) * 2 +
        ((lane & 15) * AH_LDQ + ((lane & 16) ? 8 : 0)) * 2;
    const uint32_t k_base = smb + AHOF_K * 2 +
        ((lane & 7) * AH_LDK + ((lane & 16) ? 8 * AH_LDK : 0) + ((lane & 8) ? 8 : 0)) * 2;
    const uint32_t v_base = smb + AHOF_V * 2 +
        (((lane & 7) + ((lane & 8) ? 8 : 0)) * AH_LDV + ((lane & 16) ? 8 : 0)) * 2;
    const uint32_t p_base = smb + AHOF_P * 2 + (wid * 16 * AH_LDP) * 2 +
        ((lane & 15) * AH_LDP + ((lane & 16) ? 8 : 0)) * 2;

    float m0 = neginf(), m1 = neginf();
    float l0 = 0.f, l1 = 0.f;
#pragma unroll
    for (int i = 0; i < 16; ++i)
#pragma unroll
        for (int j = 0; j < 4; ++j) acc[i][j] = 0.f;

    // each warp stages 8 rows (row = j*4 + wid); lane covers 4 halves (8B)
    uint2 rK2[8], rV2[8];
    {
        const __half* Kb = Kg + kv0 * 2048 + hoff;
        const __half* Vb = Vg + kv0 * 2048 + hoff;
#pragma unroll
        for (int j = 0; j < 8; ++j) {
            int row = j * 4 + wid;
            rK2[j] = *(const uint2*)(Kb + (size_t)row * 2048 + lane * 4);
            rV2[j] = *(const uint2*)(Vb + (size_t)row * 2048 + lane * 4);
        }
    }

    for (int kt = 0; kt < ntiles; ++kt) {
        __syncthreads();
#pragma unroll
        for (int j = 0; j < 8; ++j) {
            int row = j * 4 + wid;
            *(uint2*)(Ks + row * AH_LDK + lane * 4) = rK2[j];
            *(uint2*)(Vs + row * AH_LDV + lane * 4) = rV2[j];
        }
        __syncthreads();
        if (kt + 1 < ntiles) {
            const __half* Kb = Kg + (kv0 + (size_t)(kt + 1) * 32) * 2048 + hoff;
            const __half* Vb = Vg + (kv0 + (size_t)(kt + 1) * 32) * 2048 + hoff;
#pragma unroll
            for (int j = 0; j < 8; ++j) {
                int row = j * 4 + wid;
                rK2[j] = *(const uint2*)(Kb + (size_t)row * 2048 + lane * 4);
                rV2[j] = *(const uint2*)(Vb + (size_t)row * 2048 + lane * 4);
            }
        }

        // ---- S = Q @ K^T  (16q x 32tok per warp), 8 k16 steps ----
        float s[4][4];
#pragma unroll
        for (int ni = 0; ni < 4; ++ni)
#pragma unroll
            for (int j = 0; j < 4; ++j) s[ni][j] = 0.f;
#pragma unroll
        for (int ksA = 0; ksA < 8; ++ksA) {
            uint32_t a[4];
            ldsm4(a, q_base + ksA * 32);
#pragma unroll
            for (int np = 0; np < 2; ++np) {
                uint32_t r[4];
                ldsm4(r, k_base + (np * 16 * AH_LDK + ksA * 16) * 2);
                mma_f16(s[np * 2 + 0], a[0], a[1], a[2], a[3], r[0], r[1]);
                mma_f16(s[np * 2 + 1], a[0], a[1], a[2], a[3], r[2], r[3]);
            }
        }

        // ---- online softmax (rows g and g+8 of this warp's 16) ----
        float rm0 = neginf(), rm1 = neginf();
#pragma unroll
        for (int ni = 0; ni < 4; ++ni) {
            rm0 = fmaxf(rm0, fmaxf(s[ni][0], s[ni][1]));
            rm1 = fmaxf(rm1, fmaxf(s[ni][2], s[ni][3]));
        }
#pragma unroll
        for (int off = 1; off <= 2; off <<= 1) {
            rm0 = fmaxf(rm0, __shfl_xor_sync(0xffffffffu, rm0, off));
            rm1 = fmaxf(rm1, __shfl_xor_sync(0xffffffffu, rm1, off));
        }
        float mn0 = fmaxf(m0, rm0), mn1 = fmaxf(m1, rm1);
        float co0 = __expf(m0 - mn0), co1 = __expf(m1 - mn1);
        float rs0 = 0.f, rs1 = 0.f;
        __syncwarp();   // prior PV reads of this warp's P rows done
#pragma unroll
        for (int ni = 0; ni < 4; ++ni) {
            float p00 = __expf(s[ni][0] - mn0);
            float p01 = __expf(s[ni][1] - mn0);
            float p10 = __expf(s[ni][2] - mn1);
            float p11 = __expf(s[ni][3] - mn1);
            rs0 += p00 + p01;
            rs1 += p10 + p11;
            int pb = (wid * 16 + g) * AH_LDP + ni * 8 + 2 * c;
            *(__half2*)(Ps + pb)               = __floats2half2_rn(p00, p01);
            *(__half2*)(Ps + pb + 8 * AH_LDP)  = __floats2half2_rn(p10, p11);
        }
        __syncwarp();
#pragma unroll
        for (int off = 1; off <= 2; off <<= 1) {
            rs0 += __shfl_xor_sync(0xffffffffu, rs0, off);
            rs1 += __shfl_xor_sync(0xffffffffu, rs1, off);
        }
        l0 = l0 * co0 + rs0;
        l1 = l1 * co1 + rs1;
        m0 = mn0; m1 = mn1;
#pragma unroll
        for (int ni = 0; ni < 16; ++ni) {
            acc[ni][0] *= co0; acc[ni][1] *= co0;
            acc[ni][2] *= co1; acc[ni][3] *= co1;
        }

        // ---- O += P @ V : 2 k16 steps; V B-frags via ldmatrix.trans on [tok][d] ----
#pragma unroll
        for (int ks = 0; ks < 2; ++ks) {
            uint32_t ap[4];
            ldsm4(ap, p_base + ks * 32);
#pragma unroll
            for (int np = 0; np < 8; ++np) {
                uint32_t r[4];
                ldsm4t(r, v_base + (ks * 16 * AH_LDV + np * 16) * 2);
                mma_f16(acc[np * 2 + 0], ap[0], ap[1], ap[2], ap[3], r[0], r[1]);
                mma_f16(acc[np * 2 + 1], ap[0], ap[1], ap[2], ap[3], r[2], r[3]);
            }
        }
    }
    lout[0] = l0; lout[1] = l1;
}

__global__ __launch_bounds__(128, 4) void attn_f16_kernel(
    const __half* __restrict__ Q, const __half* __restrict__ K, const __half* __restrict__ V,
    const __half* __restrict__ KY, const __half* __restrict__ VY,
    const float* __restrict__ gate, __half* __restrict__ O)
{
    extern __shared__ __half smh[];
    __half* Qs = smh;

    const int qt = blockIdx.x, h = blockIdx.y, b = blockIdx.z;
    const int t = threadIdx.x, lane = t & 31, wid = t >> 5;
    const int g = lane >> 2, c = lane & 3;
    const int hoff = h * 128;
    const size_t qrow0 = (size_t)b * 2048 + (size_t)qt * 64;
    const uint32_t smb = (uint32_t)__cvta_generic_to_shared(smh);

    // Q fill (half, pre-scaled by LN): 64 rows x 128 halves
    const __half* Qb = Q + qrow0 * 2048 + hoff;
#pragma unroll
    for (int i = 0; i < 8; ++i) {
        int id = i * 128 + t;
        int row = id >> 4, c8 = (id & 15) * 8;
        *(uint4*)(Qs + row * AH_LDQ + c8) =
            *(const uint4*)(Qb + (size_t)row * 2048 + c8);
    }

    float acc[16][4], l[2];

    // ---- self attention ----
    attn_pass_f16(K, V, (size_t)b * 2048, 64, hoff, smh, smb, t, acc, l);
    __half* Ob = O + qrow0 * 2048 + hoff;
    {
        float inv0 = 1.f / l[0], inv1 = 1.f / l[1];
        int row = wid * 16 + g;
#pragma unroll
        for (int ni = 0; ni < 16; ++ni) {
            int col = ni * 8 + 2 * c;
            *(__half2*)(Ob + (size_t)row * 2048 + col) =
                __floats2half2_rn(acc[ni][0] * inv0, acc[ni][1] * inv0);
            *(__half2*)(Ob + (size_t)(row + 8) * 2048 + col) =
                __floats2half2_rn(acc[ni][2] * inv1, acc[ni][3] * inv1);
        }
    }

    // ---- gated cross attention (same thread re-reads its own writes) ----
    attn_pass_f16(KY, VY, (size_t)b * 512, 16, hoff, smh, smb, t, acc, l);
    {
        float tg = tanhf(gate[h]);
        float inv0 = tg / l[0], inv1 = tg / l[1];
        int row = wid * 16 + g;
#pragma unroll
        for (int ni = 0; ni < 16; ++ni) {
            int col = ni * 8 + 2 * c;
            float2 p0 = __half22float2(*(__half2*)(Ob + (size_t)row * 2048 + col));
            float2 p1 = __half22float2(*(__half2*)(Ob + (size_t)(row + 8) * 2048 + col));
            *(__half2*)(Ob + (size_t)row * 2048 + col) =
                __floats2half2_rn(p0.x + acc[ni][0] * inv0, p0.y + acc[ni][1] * inv0);
            *(__half2*)(Ob + (size_t)(row + 8) * 2048 + col) =
                __floats2half2_rn(p1.x + acc[ni][2] * inv1, p1.y + acc[ni][3] * inv1);
        }
    }
}

// -------------------------------- host side --------------------------------------
extern "C" void kernel_launch(void* const* d_in, const int* in_sizes, int n_in,
                              void* d_out, int out_size)
{
    const float* x    = (const float*)d_in[0];
    const float* fc   = (const float*)d_in[2];
    const float* y    = (const float*)d_in[3];
    const float* wq   = (const float*)d_in[5];
    const float* wk   = (const float*)d_in[6];
    const float* wv   = (const float*)d_in[7];
    const float* wo   = (const float*)d_in[8];
    const float* wky  = (const float*)d_in[9];
    const float* wvy  = (const float*)d_in[10];
    const float* gate = (const float*)d_in[11];
    const float* qnw  = (const float*)d_in[12];
    const float* qnb  = (const float*)d_in[13];
    const float* knw  = (const float*)d_in[14];
    const float* knb  = (const float*)d_in[15];
    const float* kynw = (const float*)d_in[16];
    const float* kynb = (const float*)d_in[17];
    float* out = (float*)d_out;

    float *xq, *xk, *yk;
    __half *xqh, *xkh, *ykh, *xvh, *yvh, *ath, *xth, *yth, *wth;
    cudaGetSymbolAddress((void**)&xq,  g_xq);
    cudaGetSymbolAddress((void**)&xk,  g_xk);
    cudaGetSymbolAddress((void**)&yk,  g_yk);
    cudaGetSymbolAddress((void**)&xqh, g_xqh);
    cudaGetSymbolAddress((void**)&xkh, g_xkh);
    cudaGetSymbolAddress((void**)&ykh, g_ykh);
    cudaGetSymbolAddress((void**)&xvh, g_xvh);
    cudaGetSymbolAddress((void**)&yvh, g_yvh);
    cudaGetSymbolAddress((void**)&ath, g_ath);
    cudaGetSymbolAddress((void**)&xth, g_xth);
    cudaGetSymbolAddress((void**)&yth, g_yth);
    cudaGetSymbolAddress((void**)&wth, g_wth);
    const size_t WSZ = (size_t)2048 * 2048;
    __half* wqt = wth;            __half* wkt = wth + WSZ;      __half* wvt = wth + 2 * WSZ;
    __half* wkyt = wth + 3 * WSZ; __half* wvyt = wth + 4 * WSZ; __half* wot = wth + 5 * WSZ;

    cudaFuncSetAttribute(gemm_f16_b3, cudaFuncAttributeMaxDynamicSharedMemorySize, GH_TOT * 2);
    cudaFuncSetAttribute(attn_f16_kernel, cudaFuncAttributeMaxDynamicSharedMemorySize, AH_TOT * 2);

    // #1: fused f16 round of x and y
    cvt2_f16_kernel<<<dim3(NROWS_X * 2048 / 1024, 2), 256>>>(
        x, xth, NROWS_X * 2048, y, yth, NROWS_Y * 2048);
    // #2: fused transpose+round of all 6 weights
    transpose6_f16_kernel<<<dim3(64, 64, 6), dim3(32, 8)>>>(wq, wk, wv, wky, wvy, wo, wth);
    // #3: x projections (xq, xk f32 for LN; xv half for attention)
    gemm_f16_b3<<<dim3(NH / 128, NROWS_X / 128, 3), 256, GH_TOT * 2>>>(
        xth, wqt, wkt, wvt, xq, xk, xvh, NROWS_X, NH, 2048, 0b100);
    // #4: y projections (yk f32 for LN; yv half)
    gemm_f16_b3<<<dim3(NH / 128, NROWS_Y / 128, 2), 256, GH_TOT * 2>>>(
        yth, wkyt, wvyt, wvyt, yk, yvh, yvh, NROWS_Y, NH, 2048, 0b010);
    // #5: fused layernorms (+rope); Q pre-scaled by 1/sqrt(HD); half outputs
    ln3_kernel<<<dim3(NROWS_X, 3), 256>>>(
        xq, qnw, qnb, xqh, xk, knw, knb, xkh, yk, kynw, kynb, ykh,
        fc, 0.08838834764831845f);
    // #6: fused self + gated-cross attention (fp16 mma, 4 blocks/SM)
    attn_f16_kernel<<<dim3(32, 16, 2), 128, AH_TOT * 2>>>(
        xqh, xkh, xvh, ykh, yvh, gate, ath);
    // #7: output projection (A half, C f32)
    gemm_f16_b3<<<dim3(NH / 128, NROWS_X / 128, 1), 256, GH_TOT * 2>>>(
        ath, wot, wot, wot, out, out, out, NROWS_X, NH, 2048, 0);
}